// round 2
// baseline (speedup 1.0000x reference)
#include <cuda_runtime.h>
#include <cuda_bf16.h>
#include <math.h>

// Problem constants (fixed by setup_inputs)
#define NTOK 8192
#define DIM  1024
#define HID  4096
#define NEXP 8
#define CAP  2560              // int(2 * 1.25 * 8192 / 8)
#define EC   (NEXP * CAP)      // 20480 dispatch rows

// ---------------- scratch (static __device__ globals; no allocs) -----------
__device__ float d_disp[(size_t)EC * DIM];   // dispatch buffer  (84 MB)
__device__ float d_h   [(size_t)EC * HID];   // fc1 activations (336 MB)
__device__ float d_y   [(size_t)EC * DIM];   // fc2 output       (84 MB)

__device__ int   d_e0[NTOK], d_e1[NTOK];
__device__ float d_g0[NTOK], d_g1[NTOK];
__device__ int   d_s0[NTOK], d_s1[NTOK];     // dispatch slot or -1
__device__ float d_me[NEXP];                 // sum of softmax scores per expert
__device__ int   d_cnt0[NEXP];               // top-1 histogram (uncapped)

// ---------------- kernels --------------------------------------------------

__global__ void zero_small_kernel() {
    int t = threadIdx.x;
    if (t < NEXP) { d_me[t] = 0.0f; d_cnt0[t] = 0; }
}

// warp per token: logits -> softmax -> top2 -> stats
__global__ void gate_kernel(const float* __restrict__ x,
                            const float* __restrict__ wg) {
    int warp = (blockIdx.x * blockDim.x + threadIdx.x) >> 5;
    int lane = threadIdx.x & 31;
    if (warp >= NTOK) return;

    const float* xr = x + (size_t)warp * DIM;
    float acc[NEXP];
#pragma unroll
    for (int e = 0; e < NEXP; e++) acc[e] = 0.0f;

    for (int d = lane; d < DIM; d += 32) {
        float xv = xr[d];
        const float* w = wg + (size_t)d * NEXP;
#pragma unroll
        for (int e = 0; e < NEXP; e++) acc[e] += xv * w[e];
    }
#pragma unroll
    for (int off = 16; off > 0; off >>= 1) {
#pragma unroll
        for (int e = 0; e < NEXP; e++)
            acc[e] += __shfl_xor_sync(0xFFFFFFFFu, acc[e], off);
    }

    if (lane == 0) {
        float m = acc[0];
#pragma unroll
        for (int e = 1; e < NEXP; e++) m = fmaxf(m, acc[e]);
        float p[NEXP], s = 0.0f;
#pragma unroll
        for (int e = 0; e < NEXP; e++) { p[e] = expf(acc[e] - m); s += p[e]; }
        float inv = 1.0f / s;
#pragma unroll
        for (int e = 0; e < NEXP; e++) p[e] *= inv;

        // top-2 (ties -> lower index first, matches jax.lax.top_k)
        float best = -1.0f, second = -1.0f;
        int e0 = 0, e1 = 0;
#pragma unroll
        for (int e = 0; e < NEXP; e++) {
            float v = p[e];
            if (v > best)        { second = best; e1 = e0; best = v; e0 = e; }
            else if (v > second) { second = v; e1 = e; }
        }
        d_e0[warp] = e0; d_e1[warp] = e1;
        d_g0[warp] = best; d_g1[warp] = second;

#pragma unroll
        for (int e = 0; e < NEXP; e++) atomicAdd(&d_me[e], p[e]);
        atomicAdd(&d_cnt0[e0], 1);
    }
}

// brute-force stable rank within expert (matches argsort(-g) stable):
// rank_i = #{i' : e'==e && (g'>g || (g'==g && i'<i))}
__global__ void rank_kernel() {
    __shared__ int   se0[256]; __shared__ float sg0[256];
    __shared__ int   se1[256]; __shared__ float sg1[256];

    int i = blockIdx.x * 256 + threadIdx.x;
    int   my_e0 = d_e0[i], my_e1 = d_e1[i];
    float my_g0 = d_g0[i], my_g1 = d_g1[i];
    int r0 = 0, r1 = 0;

    for (int base = 0; base < NTOK; base += 256) {
        int t = base + threadIdx.x;
        se0[threadIdx.x] = d_e0[t]; sg0[threadIdx.x] = d_g0[t];
        se1[threadIdx.x] = d_e1[t]; sg1[threadIdx.x] = d_g1[t];
        __syncthreads();
#pragma unroll 8
        for (int k = 0; k < 256; k++) {
            int tp = base + k;
            r0 += (se0[k] == my_e0) &&
                  (sg0[k] > my_g0 || (sg0[k] == my_g0 && tp < i));
            r1 += (se1[k] == my_e1) &&
                  (sg1[k] > my_g1 || (sg1[k] == my_g1 && tp < i));
        }
        __syncthreads();
    }
    int pos0 = r0;                       // j=0: offset 0
    int pos1 = r1 + d_cnt0[my_e1];       // j=1: offset = full top-1 count
    d_s0[i] = (pos0 < CAP) ? my_e0 * CAP + pos0 : -1;
    d_s1[i] = (pos1 < CAP) ? my_e1 * CAP + pos1 : -1;
}

// copy valid token rows into dispatch buffer (unique destinations, no zeroing
// needed: unassigned rows are never gathered back)
__global__ void scatter_kernel(const float* __restrict__ x) {
    int i = blockIdx.x;
    int s0 = d_s0[i], s1 = d_s1[i];
    float4 v = ((const float4*)(x + (size_t)i * DIM))[threadIdx.x];
    if (s0 >= 0) ((float4*)(d_disp + (size_t)s0 * DIM))[threadIdx.x] = v;
    if (s1 >= 0) ((float4*)(d_y))[0];  // no-op placeholder removed below
    if (s1 >= 0) ((float4*)(d_disp + (size_t)s1 * DIM))[threadIdx.x] = v;
}

__device__ __forceinline__ float gelu_exact(float v) {
    return 0.5f * v * (1.0f + erff(v * 0.70710678118654752f));
}

// tiled fp32 GEMM over the full EC x Nn output, per-expert weights.
// FC1=true : d_h = gelu(d_disp @ W1[e] + b1[e]),  K=DIM,  Nn=HID
// FC1=false: d_y =       d_h  @ W2[e] + b2[e],    K=HID,  Nn=DIM
template<int Nn, int K, bool FC1>
__global__ void gemm_kernel(const float* __restrict__ W,
                            const float* __restrict__ bias) {
    const float* __restrict__ A    = FC1 ? d_disp : d_h;
    float*       __restrict__ Cout = FC1 ? d_h    : d_y;

    __shared__ float As[16][68];   // [k][m], padded
    __shared__ float Bs[16][64];   // [k][n]

    int row0 = blockIdx.y * 64;
    int col0 = blockIdx.x * 64;
    int e = row0 / CAP;                       // 64 | CAP, block stays in one expert
    const float* Wp = W + (size_t)e * K * Nn;
    const float* bp = bias + (size_t)e * Nn;

    int tid = threadIdx.x;
    int ty = tid >> 4, tx = tid & 15;

    float acc[4][4];
#pragma unroll
    for (int i = 0; i < 4; i++)
#pragma unroll
        for (int j = 0; j < 4; j++) acc[i][j] = 0.0f;

    const float* Ap = A + (size_t)row0 * K;

    for (int k0 = 0; k0 < K; k0 += 16) {
        {   // A tile 64x16 -> transposed into As
            int r  = tid >> 2;
            int c4 = (tid & 3) * 4;
            float4 a = *(const float4*)(Ap + (size_t)r * K + k0 + c4);
            As[c4 + 0][r] = a.x; As[c4 + 1][r] = a.y;
            As[c4 + 2][r] = a.z; As[c4 + 3][r] = a.w;
        }
        {   // B tile 16x64
            int r  = tid >> 4;
            int c4 = (tid & 15) * 4;
            *(float4*)&Bs[r][c4] =
                *(const float4*)(Wp + (size_t)(k0 + r) * Nn + col0 + c4);
        }
        __syncthreads();
#pragma unroll
        for (int k = 0; k < 16; k++) {
            float a[4], b[4];
#pragma unroll
            for (int i = 0; i < 4; i++) a[i] = As[k][ty * 4 + i];
#pragma unroll
            for (int j = 0; j < 4; j++) b[j] = Bs[k][tx * 4 + j];
#pragma unroll
            for (int i = 0; i < 4; i++)
#pragma unroll
                for (int j = 0; j < 4; j++) acc[i][j] = fmaf(a[i], b[j], acc[i][j]);
        }
        __syncthreads();
    }

    float bv[4];
#pragma unroll
    for (int j = 0; j < 4; j++) bv[j] = bp[col0 + tx * 4 + j];

#pragma unroll
    for (int i = 0; i < 4; i++) {
        float4 o;
        float v0 = acc[i][0] + bv[0], v1 = acc[i][1] + bv[1];
        float v2 = acc[i][2] + bv[2], v3 = acc[i][3] + bv[3];
        if (FC1) { v0 = gelu_exact(v0); v1 = gelu_exact(v1);
                   v2 = gelu_exact(v2); v3 = gelu_exact(v3); }
        o.x = v0; o.y = v1; o.z = v2; o.w = v3;
        *(float4*)(Cout + (size_t)(row0 + ty * 4 + i) * Nn + col0 + tx * 4) = o;
    }
}

// out[i] = w0 * Y[s0] + w1 * Y[s1]   (deterministic gather, no atomics)
__global__ void combine_kernel(float* __restrict__ out) {
    int i = blockIdx.x;
    int s0 = d_s0[i], s1 = d_s1[i];
    float w0 = (s0 >= 0) ? d_g0[i] : 0.0f;
    float w1 = (s1 >= 0) ? d_g1[i] : 0.0f;
    float4 r = make_float4(0.f, 0.f, 0.f, 0.f);
    if (s0 >= 0) {
        float4 a = ((const float4*)(d_y + (size_t)s0 * DIM))[threadIdx.x];
        r.x += w0 * a.x; r.y += w0 * a.y; r.z += w0 * a.z; r.w += w0 * a.w;
    }
    if (s1 >= 0) {
        float4 a = ((const float4*)(d_y + (size_t)s1 * DIM))[threadIdx.x];
        r.x += w1 * a.x; r.y += w1 * a.y; r.z += w1 * a.z; r.w += w1 * a.w;
    }
    ((float4*)(out + (size_t)i * DIM))[threadIdx.x] = r;
}

__global__ void laux_kernel(float* __restrict__ out, int out_size) {
    if (threadIdx.x == 0 && out_size > NTOK * DIM) {
        float lx = 0.0f;
        for (int e = 0; e < NEXP; e++) {
            float me = d_me[e] / (float)NTOK;
            float ce = (float)d_cnt0[e] / (float)NTOK;
            lx += me * ce;
        }
        out[NTOK * DIM] = lx * (float)NEXP;
    }
}

// ---------------- launch ---------------------------------------------------
extern "C" void kernel_launch(void* const* d_in, const int* in_sizes, int n_in,
                              void* d_out, int out_size) {
    const float* x     = (const float*)d_in[0];
    const float* wg    = (const float*)d_in[1];
    const float* fc1_w = (const float*)d_in[2];
    const float* fc1_b = (const float*)d_in[3];
    const float* fc2_w = (const float*)d_in[4];
    const float* fc2_b = (const float*)d_in[5];
    float* out = (float*)d_out;

    zero_small_kernel<<<1, 32>>>();
    gate_kernel<<<NTOK / 8, 256>>>(x, wg);          // 8 warps/block
    rank_kernel<<<NTOK / 256, 256>>>();
    scatter_kernel<<<NTOK, 256>>>(x);

    gemm_kernel<HID, DIM, true ><<<dim3(HID / 64, EC / 64), 256>>>(fc1_w, fc1_b);
    gemm_kernel<DIM, HID, false><<<dim3(DIM / 64, EC / 64), 256>>>(fc2_w, fc2_b);

    combine_kernel<<<NTOK, 256>>>(out);
    laux_kernel<<<1, 32>>>(out, out_size);
}

// round 9
// speedup vs baseline: 1.9375x; 1.9375x over previous
#include <cuda_runtime.h>
#include <cuda_fp16.h>
#include <math.h>
#include <stdint.h>

// Problem constants (fixed by setup_inputs)
#define NTOK 8192
#define DIM  1024
#define HID  4096
#define NEXP 8
#define CAP  2560              // int(2 * 1.25 * 8192 / 8)
#define EC   (NEXP * CAP)      // 20480 dispatch rows

// ---------------- scratch (static __device__ globals; no allocs) -----------
__device__ __align__(16) float d_disp[(size_t)EC * DIM];   // 80 MB
__device__ __align__(16) float d_h   [(size_t)EC * HID];   // 320 MB
__device__ __align__(16) float d_y   [(size_t)EC * DIM];   // 80 MB

__device__ int   d_e0[NTOK], d_e1[NTOK];
__device__ float d_g0[NTOK], d_g1[NTOK];
__device__ int   d_s0[NTOK], d_s1[NTOK];     // dispatch slot or -1
__device__ float d_me[NEXP];                 // sum of softmax scores per expert
__device__ int   d_cnt0[NEXP];               // top-1 histogram (uncapped)

// ---------------- PTX helpers ----------------------------------------------
__device__ __forceinline__ uint32_t smem_u32(const void* p) {
    uint32_t a;
    asm("{ .reg .u64 t; cvta.to.shared.u64 t, %1; cvt.u32.u64 %0, t; }"
        : "=r"(a) : "l"(p));
    return a;
}
__device__ __forceinline__ void ldmat_x4(uint32_t* r, uint32_t addr) {
    asm volatile("ldmatrix.sync.aligned.m8n8.x4.shared.b16 {%0,%1,%2,%3}, [%4];"
                 : "=r"(r[0]), "=r"(r[1]), "=r"(r[2]), "=r"(r[3]) : "r"(addr));
}
__device__ __forceinline__ void ldmat_x4_t(uint32_t* r, uint32_t addr) {
    asm volatile("ldmatrix.sync.aligned.m8n8.x4.trans.shared.b16 {%0,%1,%2,%3}, [%4];"
                 : "=r"(r[0]), "=r"(r[1]), "=r"(r[2]), "=r"(r[3]) : "r"(addr));
}
__device__ __forceinline__ void mma16816(float* c, const uint32_t* a, const uint32_t* b) {
    asm volatile(
        "mma.sync.aligned.m16n8k16.row.col.f32.f16.f16.f32 "
        "{%0,%1,%2,%3}, {%4,%5,%6,%7}, {%8,%9}, {%0,%1,%2,%3};"
        : "+f"(c[0]), "+f"(c[1]), "+f"(c[2]), "+f"(c[3])
        : "r"(a[0]), "r"(a[1]), "r"(a[2]), "r"(a[3]), "r"(b[0]), "r"(b[1]));
}
__device__ __forceinline__ uint32_t pack_h2(__half a, __half b) {
    return (uint32_t)__half_as_ushort(a) | ((uint32_t)__half_as_ushort(b) << 16);
}
__device__ __forceinline__ void split_f16(float v, __half& h, __half& l) {
    h = __float2half(v);
    l = __float2half(v - __half2float(h));
}

// ---------------- small kernels --------------------------------------------
__global__ void zero_small_kernel() {
    int t = threadIdx.x;
    if (t < NEXP) { d_me[t] = 0.0f; d_cnt0[t] = 0; }
}

__global__ void gate_kernel(const float* __restrict__ x,
                            const float* __restrict__ wg) {
    int warp = (blockIdx.x * blockDim.x + threadIdx.x) >> 5;
    int lane = threadIdx.x & 31;
    if (warp >= NTOK) return;

    const float* xr = x + (size_t)warp * DIM;
    float acc[NEXP];
#pragma unroll
    for (int e = 0; e < NEXP; e++) acc[e] = 0.0f;
    for (int d = lane; d < DIM; d += 32) {
        float xv = xr[d];
        const float* w = wg + (size_t)d * NEXP;
#pragma unroll
        for (int e = 0; e < NEXP; e++) acc[e] += xv * w[e];
    }
#pragma unroll
    for (int off = 16; off > 0; off >>= 1)
#pragma unroll
        for (int e = 0; e < NEXP; e++)
            acc[e] += __shfl_xor_sync(0xFFFFFFFFu, acc[e], off);

    if (lane == 0) {
        float m = acc[0];
#pragma unroll
        for (int e = 1; e < NEXP; e++) m = fmaxf(m, acc[e]);
        float p[NEXP], s = 0.0f;
#pragma unroll
        for (int e = 0; e < NEXP; e++) { p[e] = expf(acc[e] - m); s += p[e]; }
        float inv = 1.0f / s;
#pragma unroll
        for (int e = 0; e < NEXP; e++) p[e] *= inv;

        float best = -1.0f, second = -1.0f;
        int e0 = 0, e1 = 0;
#pragma unroll
        for (int e = 0; e < NEXP; e++) {
            float v = p[e];
            if (v > best)        { second = best; e1 = e0; best = v; e0 = e; }
            else if (v > second) { second = v; e1 = e; }
        }
        d_e0[warp] = e0; d_e1[warp] = e1;
        d_g0[warp] = best; d_g1[warp] = second;
#pragma unroll
        for (int e = 0; e < NEXP; e++) atomicAdd(&d_me[e], p[e]);
        atomicAdd(&d_cnt0[e0], 1);
    }
}

__global__ void rank_kernel() {
    __shared__ int   se0[256]; __shared__ float sg0[256];
    __shared__ int   se1[256]; __shared__ float sg1[256];

    int i = blockIdx.x * 256 + threadIdx.x;
    int   my_e0 = d_e0[i], my_e1 = d_e1[i];
    float my_g0 = d_g0[i], my_g1 = d_g1[i];
    int r0 = 0, r1 = 0;

    for (int base = 0; base < NTOK; base += 256) {
        int t = base + threadIdx.x;
        se0[threadIdx.x] = d_e0[t]; sg0[threadIdx.x] = d_g0[t];
        se1[threadIdx.x] = d_e1[t]; sg1[threadIdx.x] = d_g1[t];
        __syncthreads();
#pragma unroll 8
        for (int k = 0; k < 256; k++) {
            int tp = base + k;
            r0 += (se0[k] == my_e0) && (sg0[k] > my_g0 || (sg0[k] == my_g0 && tp < i));
            r1 += (se1[k] == my_e1) && (sg1[k] > my_g1 || (sg1[k] == my_g1 && tp < i));
        }
        __syncthreads();
    }
    int pos0 = r0;
    int pos1 = r1 + d_cnt0[my_e1];
    d_s0[i] = (pos0 < CAP) ? my_e0 * CAP + pos0 : -1;
    d_s1[i] = (pos1 < CAP) ? my_e1 * CAP + pos1 : -1;
}

// fp32 scatter (identical to the round-2 passing version)
__global__ void scatter_kernel(const float* __restrict__ x) {
    int i = blockIdx.x;
    int s0 = d_s0[i], s1 = d_s1[i];
    if (s0 < 0 && s1 < 0) return;
    float4 v = ((const float4*)(x + (size_t)i * DIM))[threadIdx.x];
    if (s0 >= 0) ((float4*)(d_disp + (size_t)s0 * DIM))[threadIdx.x] = v;
    if (s1 >= 0) ((float4*)(d_disp + (size_t)s1 * DIM))[threadIdx.x] = v;
}

__device__ __forceinline__ float gelu_exact(float v) {
    return 0.5f * v * (1.0f + erff(v * 0.70710678118654752f));
}

// ---------------- mma.sync split-fp16 GEMM, STATIC smem, in-kernel split ----
// Block tile 128x128, 8 warps (warp 64m x 32n), K-chunk 32, single stage.
// A fp32 [m][k] (disp or h); B fp32 = original weights [e][k][n] (n contiguous).
// In-kernel: fp32 -> fp16 hi/lo split into padded smem; A via ldmatrix,
// B via ldmatrix.trans. C = Ah*Bh + Ah*Bl + Al*Bh (fp32 accum).
#define A_STRIDE 40     // halves per row (80 B, 16B-aligned, conflict-free)
#define B_STRIDE 136    // halves per row (272 B, 16B-aligned, conflict-free)

template<int KTOT, int NTOT, bool FC1>
__global__ void __launch_bounds__(256)
mma_gemm_kernel(const float* __restrict__ W, const float* __restrict__ bias) {
    __shared__ __half sAh[128 * A_STRIDE];   // 10240 B
    __shared__ __half sAl[128 * A_STRIDE];   // 10240 B
    __shared__ __half sBh[32 * B_STRIDE];    //  8704 B
    __shared__ __half sBl[32 * B_STRIDE];    //  8704 B  (total 37888 B)

    const float* __restrict__ A = FC1 ? d_disp : d_h;
    int tid = threadIdx.x;
    int wid = tid >> 5, lane = tid & 31;
    int wm = wid & 1, wn = wid >> 1;          // warp tile 64m x 32n

    int row0 = blockIdx.y * 128;
    int n0   = blockIdx.x * 128;
    int e    = row0 / CAP;                    // 128 | CAP
    const float* Ap = A + (size_t)row0 * KTOT;
    const float* Bp = W + (size_t)e * KTOT * NTOT;
    const float* bp = bias + (size_t)e * NTOT;

    uint32_t aAh = smem_u32(sAh), aAl = smem_u32(sAl);
    uint32_t aBh = smem_u32(sBh), aBl = smem_u32(sBl);

    float acc[4][4][4];
#pragma unroll
    for (int mi = 0; mi < 4; mi++)
#pragma unroll
        for (int ni = 0; ni < 4; ni++)
#pragma unroll
            for (int q = 0; q < 4; q++) acc[mi][ni][q] = 0.0f;

    const int arow = tid >> 3;            // 0..31
    const int ac4  = (tid & 7) * 4;       // 0..28
    const int brow = tid >> 3;            // 0..31 (k row)
    const int bc4  = (tid & 7) * 4;       // base col

    for (int ch = 0; ch < KTOT / 32; ch++) {
        // ---- A chunk: 128 rows x 32 k (fp32 -> hi/lo) ----
#pragma unroll
        for (int it = 0; it < 4; it++) {
            int r = arow + it * 32;
            float4 v = *(const float4*)(Ap + (size_t)r * KTOT + ch * 32 + ac4);
            __half h0, l0, h1, l1, h2, l2, h3, l3;
            split_f16(v.x, h0, l0); split_f16(v.y, h1, l1);
            split_f16(v.z, h2, l2); split_f16(v.w, h3, l3);
            uint2* ph = (uint2*)&sAh[r * A_STRIDE + ac4];
            uint2* pl = (uint2*)&sAl[r * A_STRIDE + ac4];
            *ph = make_uint2(pack_h2(h0, h1), pack_h2(h2, h3));
            *pl = make_uint2(pack_h2(l0, l1), pack_h2(l2, l3));
        }
        // ---- B chunk: 32 k-rows x 128 n (fp32 -> hi/lo), n contiguous ----
#pragma unroll
        for (int it = 0; it < 4; it++) {
            int c = bc4 + it * 32;
            float4 v = *(const float4*)(Bp + (size_t)(ch * 32 + brow) * NTOT + n0 + c);
            __half h0, l0, h1, l1, h2, l2, h3, l3;
            split_f16(v.x, h0, l0); split_f16(v.y, h1, l1);
            split_f16(v.z, h2, l2); split_f16(v.w, h3, l3);
            uint2* ph = (uint2*)&sBh[brow * B_STRIDE + c];
            uint2* pl = (uint2*)&sBl[brow * B_STRIDE + c];
            *ph = make_uint2(pack_h2(h0, h1), pack_h2(h2, h3));
            *pl = make_uint2(pack_h2(l0, l1), pack_h2(l2, l3));
        }
        __syncthreads();

        // ---- compute: 2 k16 steps ----
#pragma unroll
        for (int ks = 0; ks < 2; ks++) {
            uint32_t ah[4][4], al[4][4];
#pragma unroll
            for (int mi = 0; mi < 4; mi++) {
                int r = wm * 64 + mi * 16 + (lane & 15);
                uint32_t off = (uint32_t)(r * (A_STRIDE * 2) + ks * 32 + ((lane >> 4) << 4));
                ldmat_x4(ah[mi], aAh + off);
                ldmat_x4(al[mi], aAl + off);
            }
#pragma unroll
            for (int p = 0; p < 2; p++) {
                // trans ldmatrix: 4 matrices (k half, n half) for ni = 2p, 2p+1
                int j = lane >> 3, i = lane & 7;
                int kk = ks * 16 + (j & 1) * 8 + i;
                int nn = wn * 32 + p * 16 + (j >> 1) * 8;
                uint32_t off = (uint32_t)(kk * (B_STRIDE * 2) + nn * 2);
                uint32_t bh4[4], bl4[4];
                ldmat_x4_t(bh4, aBh + off);
                ldmat_x4_t(bl4, aBl + off);
#pragma unroll
                for (int ni2 = 0; ni2 < 2; ni2++) {
                    int ni = p * 2 + ni2;
                    const uint32_t* bhp = &bh4[ni2 * 2];
                    const uint32_t* blp = &bl4[ni2 * 2];
#pragma unroll
                    for (int mi = 0; mi < 4; mi++) {
                        mma16816(acc[mi][ni], ah[mi], bhp);
                        mma16816(acc[mi][ni], ah[mi], blp);
                        mma16816(acc[mi][ni], al[mi], bhp);
                    }
                }
            }
        }
        __syncthreads();
    }

    // ---- epilogue: bias (+gelu for FC1), fp32 stores ----
#pragma unroll
    for (int mi = 0; mi < 4; mi++) {
        int rbase = row0 + wm * 64 + mi * 16 + (lane >> 2);
#pragma unroll
        for (int ni = 0; ni < 4; ni++) {
            int col_l = wn * 32 + ni * 8 + ((lane & 3) << 1);
            float b0 = bp[n0 + col_l], b1 = bp[n0 + col_l + 1];
#pragma unroll
            for (int hh = 0; hh < 2; hh++) {
                int row = rbase + hh * 8;
                float v0 = acc[mi][ni][hh * 2]     + b0;
                float v1 = acc[mi][ni][hh * 2 + 1] + b1;
                size_t g = (size_t)row * NTOT + n0 + col_l;
                if (FC1) {
                    v0 = gelu_exact(v0); v1 = gelu_exact(v1);
                    *(float2*)(d_h + g) = make_float2(v0, v1);
                } else {
                    *(float2*)(d_y + g) = make_float2(v0, v1);
                }
            }
        }
    }
}

// out[i] = w0 * Y[s0] + w1 * Y[s1]   (identical to round-2 passing version)
__global__ void combine_kernel(float* __restrict__ out) {
    int i = blockIdx.x;
    int s0 = d_s0[i], s1 = d_s1[i];
    float w0 = (s0 >= 0) ? d_g0[i] : 0.0f;
    float w1 = (s1 >= 0) ? d_g1[i] : 0.0f;
    float4 r = make_float4(0.f, 0.f, 0.f, 0.f);
    if (s0 >= 0) {
        float4 a = ((const float4*)(d_y + (size_t)s0 * DIM))[threadIdx.x];
        r.x += w0 * a.x; r.y += w0 * a.y; r.z += w0 * a.z; r.w += w0 * a.w;
    }
    if (s1 >= 0) {
        float4 a = ((const float4*)(d_y + (size_t)s1 * DIM))[threadIdx.x];
        r.x += w1 * a.x; r.y += w1 * a.y; r.z += w1 * a.z; r.w += w1 * a.w;
    }
    ((float4*)(out + (size_t)i * DIM))[threadIdx.x] = r;
}

__global__ void laux_kernel(float* __restrict__ out, int out_size) {
    if (threadIdx.x == 0 && out_size > NTOK * DIM) {
        float lx = 0.0f;
        for (int e = 0; e < NEXP; e++) {
            float me = d_me[e] / (float)NTOK;
            float ce = (float)d_cnt0[e] / (float)NTOK;
            lx += me * ce;
        }
        out[NTOK * DIM] = lx * (float)NEXP;
    }
}

// ---------------- launch ---------------------------------------------------
extern "C" void kernel_launch(void* const* d_in, const int* in_sizes, int n_in,
                              void* d_out, int out_size) {
    const float* x     = (const float*)d_in[0];
    const float* wg    = (const float*)d_in[1];
    const float* fc1_w = (const float*)d_in[2];
    const float* fc1_b = (const float*)d_in[3];
    const float* fc2_w = (const float*)d_in[4];
    const float* fc2_b = (const float*)d_in[5];
    float* out = (float*)d_out;

    zero_small_kernel<<<1, 32>>>();
    gate_kernel<<<NTOK / 8, 256>>>(x, wg);
    rank_kernel<<<NTOK / 256, 256>>>();
    scatter_kernel<<<NTOK, 256>>>(x);

    // FC1: A=d_disp [EC][DIM], B=fc1_w [E][DIM][HID] -> d_h (gelu+bias)
    mma_gemm_kernel<DIM, HID, true><<<dim3(HID / 128, EC / 128), 256>>>(fc1_w, fc1_b);
    // FC2: A=d_h [EC][HID],   B=fc2_w [E][HID][DIM] -> d_y (bias)
    mma_gemm_kernel<HID, DIM, false><<<dim3(DIM / 128, EC / 128), 256>>>(fc2_w, fc2_b);

    combine_kernel<<<NTOK, 256>>>(out);
    laux_kernel<<<1, 32>>>(out, out_size);
}

// round 11
// speedup vs baseline: 2.5415x; 1.3117x over previous
#include <cuda_runtime.h>
#include <cuda_fp16.h>
#include <math.h>
#include <stdint.h>

// Problem constants (fixed by setup_inputs)
#define NTOK 8192
#define DIM  1024
#define HID  4096
#define NEXP 8
#define CAP  2560              // int(2 * 1.25 * 8192 / 8)
#define EC   (NEXP * CAP)      // 20480 dispatch rows

// ---------------- scratch (static __device__ globals; no allocs) -----------
__device__ __align__(16) float d_disp[(size_t)EC * DIM];   // 80 MB
__device__ __align__(16) float d_h   [(size_t)EC * HID];   // 320 MB
__device__ __align__(16) float d_y   [(size_t)EC * DIM];   // 80 MB

__device__ int   d_e0[NTOK], d_e1[NTOK];
__device__ float d_g0[NTOK], d_g1[NTOK];
__device__ int   d_s0[NTOK], d_s1[NTOK];     // dispatch slot or -1
__device__ float d_me[NEXP];                 // sum of softmax scores per expert
__device__ int   d_cnt0[NEXP];               // top-1 histogram (uncapped)

// ---------------- PTX helpers ----------------------------------------------
__device__ __forceinline__ uint32_t smem_u32(const void* p) {
    uint32_t a;
    asm("{ .reg .u64 t; cvta.to.shared.u64 t, %1; cvt.u32.u64 %0, t; }"
        : "=r"(a) : "l"(p));
    return a;
}
__device__ __forceinline__ void ldmat_x4(uint32_t* r, uint32_t addr) {
    asm volatile("ldmatrix.sync.aligned.m8n8.x4.shared.b16 {%0,%1,%2,%3}, [%4];"
                 : "=r"(r[0]), "=r"(r[1]), "=r"(r[2]), "=r"(r[3]) : "r"(addr));
}
__device__ __forceinline__ void ldmat_x4_t(uint32_t* r, uint32_t addr) {
    asm volatile("ldmatrix.sync.aligned.m8n8.x4.trans.shared.b16 {%0,%1,%2,%3}, [%4];"
                 : "=r"(r[0]), "=r"(r[1]), "=r"(r[2]), "=r"(r[3]) : "r"(addr));
}
__device__ __forceinline__ void mma16816(float* c, const uint32_t* a, const uint32_t* b) {
    asm volatile(
        "mma.sync.aligned.m16n8k16.row.col.f32.f16.f16.f32 "
        "{%0,%1,%2,%3}, {%4,%5,%6,%7}, {%8,%9}, {%0,%1,%2,%3};"
        : "+f"(c[0]), "+f"(c[1]), "+f"(c[2]), "+f"(c[3])
        : "r"(a[0]), "r"(a[1]), "r"(a[2]), "r"(a[3]), "r"(b[0]), "r"(b[1]));
}
__device__ __forceinline__ uint32_t pack_h2(__half a, __half b) {
    return (uint32_t)__half_as_ushort(a) | ((uint32_t)__half_as_ushort(b) << 16);
}
__device__ __forceinline__ void split_f16(float v, __half& h, __half& l) {
    h = __float2half(v);
    l = __float2half(v - __half2float(h));
}

// ---------------- small kernels --------------------------------------------
__global__ void zero_small_kernel() {
    int t = threadIdx.x;
    if (t < NEXP) { d_me[t] = 0.0f; d_cnt0[t] = 0; }
}

__global__ void gate_kernel(const float* __restrict__ x,
                            const float* __restrict__ wg) {
    int warp = (blockIdx.x * blockDim.x + threadIdx.x) >> 5;
    int lane = threadIdx.x & 31;
    if (warp >= NTOK) return;

    const float* xr = x + (size_t)warp * DIM;
    float acc[NEXP];
#pragma unroll
    for (int e = 0; e < NEXP; e++) acc[e] = 0.0f;
    for (int d = lane; d < DIM; d += 32) {
        float xv = xr[d];
        const float* w = wg + (size_t)d * NEXP;
#pragma unroll
        for (int e = 0; e < NEXP; e++) acc[e] += xv * w[e];
    }
#pragma unroll
    for (int off = 16; off > 0; off >>= 1)
#pragma unroll
        for (int e = 0; e < NEXP; e++)
            acc[e] += __shfl_xor_sync(0xFFFFFFFFu, acc[e], off);

    if (lane == 0) {
        float m = acc[0];
#pragma unroll
        for (int e = 1; e < NEXP; e++) m = fmaxf(m, acc[e]);
        float p[NEXP], s = 0.0f;
#pragma unroll
        for (int e = 0; e < NEXP; e++) { p[e] = expf(acc[e] - m); s += p[e]; }
        float inv = 1.0f / s;
#pragma unroll
        for (int e = 0; e < NEXP; e++) p[e] *= inv;

        float best = -1.0f, second = -1.0f;
        int e0 = 0, e1 = 0;
#pragma unroll
        for (int e = 0; e < NEXP; e++) {
            float v = p[e];
            if (v > best)        { second = best; e1 = e0; best = v; e0 = e; }
            else if (v > second) { second = v; e1 = e; }
        }
        d_e0[warp] = e0; d_e1[warp] = e1;
        d_g0[warp] = best; d_g1[warp] = second;
#pragma unroll
        for (int e = 0; e < NEXP; e++) atomicAdd(&d_me[e], p[e]);
        atomicAdd(&d_cnt0[e0], 1);
    }
}

__global__ void rank_kernel() {
    __shared__ int   se0[256]; __shared__ float sg0[256];
    __shared__ int   se1[256]; __shared__ float sg1[256];

    int i = blockIdx.x * 256 + threadIdx.x;
    int   my_e0 = d_e0[i], my_e1 = d_e1[i];
    float my_g0 = d_g0[i], my_g1 = d_g1[i];
    int r0 = 0, r1 = 0;

    for (int base = 0; base < NTOK; base += 256) {
        int t = base + threadIdx.x;
        se0[threadIdx.x] = d_e0[t]; sg0[threadIdx.x] = d_g0[t];
        se1[threadIdx.x] = d_e1[t]; sg1[threadIdx.x] = d_g1[t];
        __syncthreads();
#pragma unroll 8
        for (int k = 0; k < 256; k++) {
            int tp = base + k;
            r0 += (se0[k] == my_e0) && (sg0[k] > my_g0 || (sg0[k] == my_g0 && tp < i));
            r1 += (se1[k] == my_e1) && (sg1[k] > my_g1 || (sg1[k] == my_g1 && tp < i));
        }
        __syncthreads();
    }
    int pos0 = r0;
    int pos1 = r1 + d_cnt0[my_e1];
    d_s0[i] = (pos0 < CAP) ? my_e0 * CAP + pos0 : -1;
    d_s1[i] = (pos1 < CAP) ? my_e1 * CAP + pos1 : -1;
}

// fp32 scatter (identical to passing round-9 version)
__global__ void scatter_kernel(const float* __restrict__ x) {
    int i = blockIdx.x;
    int s0 = d_s0[i], s1 = d_s1[i];
    if (s0 < 0 && s1 < 0) return;
    float4 v = ((const float4*)(x + (size_t)i * DIM))[threadIdx.x];
    if (s0 >= 0) ((float4*)(d_disp + (size_t)s0 * DIM))[threadIdx.x] = v;
    if (s1 >= 0) ((float4*)(d_disp + (size_t)s1 * DIM))[threadIdx.x] = v;
}

__device__ __forceinline__ float gelu_exact(float v) {
    return 0.5f * v * (1.0f + erff(v * 0.70710678118654752f));
}

// ---------------- mma.sync 2-term GEMM, static smem, register prefetch -----
// Block tile 128x128, 8 warps (warp 64m x 32n), K-chunk 32, single smem stage
// with LDG register prefetch of the next chunk issued before compute.
// A fp32 [m][k] split in-kernel to fp16 hi/lo (exact); B fp32 [e][k][n]
// rounded to single fp16.  C = (Ah + Al) * Bh, fp32 accum.
#define A_STRIDE 40     // halves per A row (80 B, 16B-aligned, conflict-free)
#define B_STRIDE 136    // halves per B row (272 B, 16B-aligned, conflict-free)

template<int KTOT, int NTOT, bool FC1>
__global__ void __launch_bounds__(256)
mma_gemm_kernel(const float* __restrict__ W, const float* __restrict__ bias) {
    __shared__ __half sAh[128 * A_STRIDE];   // 10240 B
    __shared__ __half sAl[128 * A_STRIDE];   // 10240 B
    __shared__ __half sBh[32 * B_STRIDE];    //  8704 B  (total 29184 B static)

    const float* __restrict__ A = FC1 ? d_disp : d_h;
    int tid = threadIdx.x;
    int wid = tid >> 5, lane = tid & 31;
    int wm = wid & 1, wn = wid >> 1;          // warp tile 64m x 32n

    int row0 = blockIdx.y * 128;
    int n0   = blockIdx.x * 128;
    int e    = row0 / CAP;                    // 128 | CAP
    const float* Ap = A + (size_t)row0 * KTOT;
    const float* Bp = W + (size_t)e * KTOT * NTOT;
    const float* bp = bias + (size_t)e * NTOT;

    uint32_t aAh = smem_u32(sAh), aAl = smem_u32(sAl);
    uint32_t aBh = smem_u32(sBh);

    float acc[4][4][4];
#pragma unroll
    for (int mi = 0; mi < 4; mi++)
#pragma unroll
        for (int ni = 0; ni < 4; ni++)
#pragma unroll
            for (int q = 0; q < 4; q++) acc[mi][ni][q] = 0.0f;

    const int arow = tid >> 3;            // 0..31
    const int ac4  = (tid & 7) * 4;       // 0..28
    const int brow = tid >> 3;            // 0..31 (k row)
    const int bc4  = (tid & 7) * 4;       // base col

    constexpr int NCH = KTOT / 32;

    float4 aReg[4], bReg[4];
    // prologue: load chunk 0 into registers
#pragma unroll
    for (int it = 0; it < 4; it++)
        aReg[it] = *(const float4*)(Ap + (size_t)(arow + it * 32) * KTOT + ac4);
#pragma unroll
    for (int it = 0; it < 4; it++)
        bReg[it] = *(const float4*)(Bp + (size_t)brow * NTOT + n0 + bc4 + it * 32);

    for (int ch = 0; ch < NCH; ch++) {
        // ---- split regs -> smem ----
#pragma unroll
        for (int it = 0; it < 4; it++) {
            int r = arow + it * 32;
            float4 v = aReg[it];
            __half h0, l0, h1, l1, h2, l2, h3, l3;
            split_f16(v.x, h0, l0); split_f16(v.y, h1, l1);
            split_f16(v.z, h2, l2); split_f16(v.w, h3, l3);
            *(uint2*)&sAh[r * A_STRIDE + ac4] = make_uint2(pack_h2(h0, h1), pack_h2(h2, h3));
            *(uint2*)&sAl[r * A_STRIDE + ac4] = make_uint2(pack_h2(l0, l1), pack_h2(l2, l3));
        }
#pragma unroll
        for (int it = 0; it < 4; it++) {
            int c = bc4 + it * 32;
            float4 v = bReg[it];
            *(uint2*)&sBh[brow * B_STRIDE + c] =
                make_uint2(pack_h2(__float2half(v.x), __float2half(v.y)),
                           pack_h2(__float2half(v.z), __float2half(v.w)));
        }
        __syncthreads();

        // ---- prefetch next chunk into registers (LDG in flight over compute) ----
        if (ch + 1 < NCH) {
            int kn = (ch + 1) * 32;
#pragma unroll
            for (int it = 0; it < 4; it++)
                aReg[it] = *(const float4*)(Ap + (size_t)(arow + it * 32) * KTOT + kn + ac4);
#pragma unroll
            for (int it = 0; it < 4; it++)
                bReg[it] = *(const float4*)(Bp + (size_t)(kn + brow) * NTOT + n0 + bc4 + it * 32);
        }

        // ---- compute: 2 k16 steps, 2 terms ----
#pragma unroll
        for (int ks = 0; ks < 2; ks++) {
            uint32_t ah[4][4], al[4][4];
#pragma unroll
            for (int mi = 0; mi < 4; mi++) {
                int r = wm * 64 + mi * 16 + (lane & 15);
                uint32_t off = (uint32_t)(r * (A_STRIDE * 2) + ks * 32 + ((lane >> 4) << 4));
                ldmat_x4(ah[mi], aAh + off);
                ldmat_x4(al[mi], aAl + off);
            }
#pragma unroll
            for (int p = 0; p < 2; p++) {
                int j = lane >> 3, i = lane & 7;
                int kk = ks * 16 + (j & 1) * 8 + i;
                int nn = wn * 32 + p * 16 + (j >> 1) * 8;
                uint32_t off = (uint32_t)(kk * (B_STRIDE * 2) + nn * 2);
                uint32_t b4[4];
                ldmat_x4_t(b4, aBh + off);
#pragma unroll
                for (int ni2 = 0; ni2 < 2; ni2++) {
                    int ni = p * 2 + ni2;
                    const uint32_t* bp2 = &b4[ni2 * 2];
#pragma unroll
                    for (int mi = 0; mi < 4; mi++) {
                        mma16816(acc[mi][ni], ah[mi], bp2);
                        mma16816(acc[mi][ni], al[mi], bp2);
                    }
                }
            }
        }
        __syncthreads();
    }

    // ---- epilogue: bias (+gelu for FC1), fp32 stores ----
#pragma unroll
    for (int mi = 0; mi < 4; mi++) {
        int rbase = row0 + wm * 64 + mi * 16 + (lane >> 2);
#pragma unroll
        for (int ni = 0; ni < 4; ni++) {
            int col_l = wn * 32 + ni * 8 + ((lane & 3) << 1);
            float b0 = bp[n0 + col_l], b1 = bp[n0 + col_l + 1];
#pragma unroll
            for (int hh = 0; hh < 2; hh++) {
                int row = rbase + hh * 8;
                float v0 = acc[mi][ni][hh * 2]     + b0;
                float v1 = acc[mi][ni][hh * 2 + 1] + b1;
                size_t g = (size_t)row * NTOT + n0 + col_l;
                if (FC1) {
                    v0 = gelu_exact(v0); v1 = gelu_exact(v1);
                    *(float2*)(d_h + g) = make_float2(v0, v1);
                } else {
                    *(float2*)(d_y + g) = make_float2(v0, v1);
                }
            }
        }
    }
}

// out[i] = w0 * Y[s0] + w1 * Y[s1]
__global__ void combine_kernel(float* __restrict__ out) {
    int i = blockIdx.x;
    int s0 = d_s0[i], s1 = d_s1[i];
    float w0 = (s0 >= 0) ? d_g0[i] : 0.0f;
    float w1 = (s1 >= 0) ? d_g1[i] : 0.0f;
    float4 r = make_float4(0.f, 0.f, 0.f, 0.f);
    if (s0 >= 0) {
        float4 a = ((const float4*)(d_y + (size_t)s0 * DIM))[threadIdx.x];
        r.x += w0 * a.x; r.y += w0 * a.y; r.z += w0 * a.z; r.w += w0 * a.w;
    }
    if (s1 >= 0) {
        float4 a = ((const float4*)(d_y + (size_t)s1 * DIM))[threadIdx.x];
        r.x += w1 * a.x; r.y += w1 * a.y; r.z += w1 * a.z; r.w += w1 * a.w;
    }
    ((float4*)(out + (size_t)i * DIM))[threadIdx.x] = r;
}

__global__ void laux_kernel(float* __restrict__ out, int out_size) {
    if (threadIdx.x == 0 && out_size > NTOK * DIM) {
        float lx = 0.0f;
        for (int e = 0; e < NEXP; e++) {
            float me = d_me[e] / (float)NTOK;
            float ce = (float)d_cnt0[e] / (float)NTOK;
            lx += me * ce;
        }
        out[NTOK * DIM] = lx * (float)NEXP;
    }
}

// ---------------- launch ---------------------------------------------------
extern "C" void kernel_launch(void* const* d_in, const int* in_sizes, int n_in,
                              void* d_out, int out_size) {
    const float* x     = (const float*)d_in[0];
    const float* wg    = (const float*)d_in[1];
    const float* fc1_w = (const float*)d_in[2];
    const float* fc1_b = (const float*)d_in[3];
    const float* fc2_w = (const float*)d_in[4];
    const float* fc2_b = (const float*)d_in[5];
    float* out = (float*)d_out;

    zero_small_kernel<<<1, 32>>>();
    gate_kernel<<<NTOK / 8, 256>>>(x, wg);
    rank_kernel<<<NTOK / 256, 256>>>();
    scatter_kernel<<<NTOK, 256>>>(x);

    // FC1: A=d_disp [EC][DIM], B=fc1_w [E][DIM][HID] -> d_h (gelu+bias)
    mma_gemm_kernel<DIM, HID, true><<<dim3(HID / 128, EC / 128), 256>>>(fc1_w, fc1_b);
    // FC2: A=d_h [EC][HID],   B=fc2_w [E][HID][DIM] -> d_y (bias)
    mma_gemm_kernel<HID, DIM, false><<<dim3(DIM / 128, EC / 128), 256>>>(fc2_w, fc2_b);

    combine_kernel<<<NTOK, 256>>>(out);
    laux_kernel<<<1, 32>>>(out, out_size);
}

// round 13
// speedup vs baseline: 3.9581x; 1.5574x over previous
#include <cuda_runtime.h>
#include <cuda_fp16.h>
#include <math.h>
#include <stdint.h>

// Problem constants (fixed by setup_inputs)
#define NTOK 8192
#define DIM  1024
#define HID  4096
#define NEXP 8
#define CAP  2560              // int(2 * 1.25 * 8192 / 8)
#define EC   (NEXP * CAP)      // 20480 dispatch rows

// ---------------- scratch (static __device__ globals; no allocs) -----------
__device__ __align__(16) float d_disp[(size_t)EC * DIM];   // 80 MB
__device__ __align__(16) float d_h   [(size_t)EC * HID];   // 320 MB
__device__ __align__(16) float d_y   [(size_t)EC * DIM];   // 80 MB

__device__ int   d_e0[NTOK], d_e1[NTOK];
__device__ float d_g0[NTOK], d_g1[NTOK];
__device__ int   d_s0[NTOK], d_s1[NTOK];     // dispatch slot or -1
__device__ float d_me[NEXP];                 // sum of softmax scores per expert
__device__ int   d_cnt0[NEXP];               // top-1 histogram (uncapped)

// ---------------- PTX helpers ----------------------------------------------
__device__ __forceinline__ uint32_t smem_u32(const void* p) {
    uint32_t a;
    asm("{ .reg .u64 t; cvta.to.shared.u64 t, %1; cvt.u32.u64 %0, t; }"
        : "=r"(a) : "l"(p));
    return a;
}
__device__ __forceinline__ void ldmat_x4(uint32_t* r, uint32_t addr) {
    asm volatile("ldmatrix.sync.aligned.m8n8.x4.shared.b16 {%0,%1,%2,%3}, [%4];"
                 : "=r"(r[0]), "=r"(r[1]), "=r"(r[2]), "=r"(r[3]) : "r"(addr));
}
__device__ __forceinline__ void ldmat_x4_t(uint32_t* r, uint32_t addr) {
    asm volatile("ldmatrix.sync.aligned.m8n8.x4.trans.shared.b16 {%0,%1,%2,%3}, [%4];"
                 : "=r"(r[0]), "=r"(r[1]), "=r"(r[2]), "=r"(r[3]) : "r"(addr));
}
__device__ __forceinline__ void mma16816(float* c, const uint32_t* a, const uint32_t* b) {
    asm volatile(
        "mma.sync.aligned.m16n8k16.row.col.f32.f16.f16.f32 "
        "{%0,%1,%2,%3}, {%4,%5,%6,%7}, {%8,%9}, {%0,%1,%2,%3};"
        : "+f"(c[0]), "+f"(c[1]), "+f"(c[2]), "+f"(c[3])
        : "r"(a[0]), "r"(a[1]), "r"(a[2]), "r"(a[3]), "r"(b[0]), "r"(b[1]));
}
__device__ __forceinline__ uint32_t pack_h2(__half a, __half b) {
    return (uint32_t)__half_as_ushort(a) | ((uint32_t)__half_as_ushort(b) << 16);
}

// ---------------- small kernels --------------------------------------------
__global__ void zero_small_kernel() {
    int t = threadIdx.x;
    if (t < NEXP) { d_me[t] = 0.0f; d_cnt0[t] = 0; }
}

__global__ void gate_kernel(const float* __restrict__ x,
                            const float* __restrict__ wg) {
    int warp = (blockIdx.x * blockDim.x + threadIdx.x) >> 5;
    int lane = threadIdx.x & 31;
    if (warp >= NTOK) return;

    const float* xr = x + (size_t)warp * DIM;
    float acc[NEXP];
#pragma unroll
    for (int e = 0; e < NEXP; e++) acc[e] = 0.0f;
    for (int d = lane; d < DIM; d += 32) {
        float xv = xr[d];
        const float* w = wg + (size_t)d * NEXP;
#pragma unroll
        for (int e = 0; e < NEXP; e++) acc[e] += xv * w[e];
    }
#pragma unroll
    for (int off = 16; off > 0; off >>= 1)
#pragma unroll
        for (int e = 0; e < NEXP; e++)
            acc[e] += __shfl_xor_sync(0xFFFFFFFFu, acc[e], off);

    if (lane == 0) {
        float m = acc[0];
#pragma unroll
        for (int e = 1; e < NEXP; e++) m = fmaxf(m, acc[e]);
        float p[NEXP], s = 0.0f;
#pragma unroll
        for (int e = 0; e < NEXP; e++) { p[e] = expf(acc[e] - m); s += p[e]; }
        float inv = 1.0f / s;
#pragma unroll
        for (int e = 0; e < NEXP; e++) p[e] *= inv;

        float best = -1.0f, second = -1.0f;
        int e0 = 0, e1 = 0;
#pragma unroll
        for (int e = 0; e < NEXP; e++) {
            float v = p[e];
            if (v > best)        { second = best; e1 = e0; best = v; e0 = e; }
            else if (v > second) { second = v; e1 = e; }
        }
        d_e0[warp] = e0; d_e1[warp] = e1;
        d_g0[warp] = best; d_g1[warp] = second;
#pragma unroll
        for (int e = 0; e < NEXP; e++) atomicAdd(&d_me[e], p[e]);
        atomicAdd(&d_cnt0[e0], 1);
    }
}

__global__ void rank_kernel() {
    __shared__ int   se0[256]; __shared__ float sg0[256];
    __shared__ int   se1[256]; __shared__ float sg1[256];

    int i = blockIdx.x * 256 + threadIdx.x;
    int   my_e0 = d_e0[i], my_e1 = d_e1[i];
    float my_g0 = d_g0[i], my_g1 = d_g1[i];
    int r0 = 0, r1 = 0;

    for (int base = 0; base < NTOK; base += 256) {
        int t = base + threadIdx.x;
        se0[threadIdx.x] = d_e0[t]; sg0[threadIdx.x] = d_g0[t];
        se1[threadIdx.x] = d_e1[t]; sg1[threadIdx.x] = d_g1[t];
        __syncthreads();
#pragma unroll 8
        for (int k = 0; k < 256; k++) {
            int tp = base + k;
            r0 += (se0[k] == my_e0) && (sg0[k] > my_g0 || (sg0[k] == my_g0 && tp < i));
            r1 += (se1[k] == my_e1) && (sg1[k] > my_g1 || (sg1[k] == my_g1 && tp < i));
        }
        __syncthreads();
    }
    int pos0 = r0;
    int pos1 = r1 + d_cnt0[my_e1];
    d_s0[i] = (pos0 < CAP) ? my_e0 * CAP + pos0 : -1;
    d_s1[i] = (pos1 < CAP) ? my_e1 * CAP + pos1 : -1;
}

// fp32 scatter (identical to passing round-11 version)
__global__ void scatter_kernel(const float* __restrict__ x) {
    int i = blockIdx.x;
    int s0 = d_s0[i], s1 = d_s1[i];
    if (s0 < 0 && s1 < 0) return;
    float4 v = ((const float4*)(x + (size_t)i * DIM))[threadIdx.x];
    if (s0 >= 0) ((float4*)(d_disp + (size_t)s0 * DIM))[threadIdx.x] = v;
    if (s1 >= 0) ((float4*)(d_disp + (size_t)s1 * DIM))[threadIdx.x] = v;
}

__device__ __forceinline__ float gelu_exact(float v) {
    return 0.5f * v * (1.0f + erff(v * 0.70710678118654752f));
}

// ---------------- mma.sync 1-term fp16 GEMM, static smem, reg prefetch ------
// Block tile 128x128, 8 warps (warp 64m x 32n), K-chunk 32, single smem stage
// with LDG register prefetch of the next chunk issued before compute.
// A fp32 [m][k] rounded in-kernel to fp16; B fp32 [e][k][n] rounded to fp16.
// C = Ah * Bh, fp32 accum.  (Structure identical to round-11 pass, minus lo.)
#define A_STRIDE 40     // halves per A row (80 B, 16B-aligned, conflict-free)
#define B_STRIDE 136    // halves per B row (272 B, 16B-aligned, conflict-free)

template<int KTOT, int NTOT, bool FC1>
__global__ void __launch_bounds__(256)
mma_gemm_kernel(const float* __restrict__ W, const float* __restrict__ bias) {
    __shared__ __half sAh[128 * A_STRIDE];   // 10240 B
    __shared__ __half sBh[32 * B_STRIDE];    //  8704 B  (total 18944 B static)

    const float* __restrict__ A = FC1 ? d_disp : d_h;
    int tid = threadIdx.x;
    int wid = tid >> 5, lane = tid & 31;
    int wm = wid & 1, wn = wid >> 1;          // warp tile 64m x 32n

    int row0 = blockIdx.y * 128;
    int n0   = blockIdx.x * 128;
    int e    = row0 / CAP;                    // 128 | CAP
    const float* Ap = A + (size_t)row0 * KTOT;
    const float* Bp = W + (size_t)e * KTOT * NTOT;
    const float* bp = bias + (size_t)e * NTOT;

    uint32_t aAh = smem_u32(sAh);
    uint32_t aBh = smem_u32(sBh);

    float acc[4][4][4];
#pragma unroll
    for (int mi = 0; mi < 4; mi++)
#pragma unroll
        for (int ni = 0; ni < 4; ni++)
#pragma unroll
            for (int q = 0; q < 4; q++) acc[mi][ni][q] = 0.0f;

    const int arow = tid >> 3;            // 0..31
    const int ac4  = (tid & 7) * 4;       // 0..28
    const int brow = tid >> 3;            // 0..31 (k row)
    const int bc4  = (tid & 7) * 4;       // base col

    constexpr int NCH = KTOT / 32;

    float4 aReg[4], bReg[4];
    // prologue: load chunk 0 into registers
#pragma unroll
    for (int it = 0; it < 4; it++)
        aReg[it] = *(const float4*)(Ap + (size_t)(arow + it * 32) * KTOT + ac4);
#pragma unroll
    for (int it = 0; it < 4; it++)
        bReg[it] = *(const float4*)(Bp + (size_t)brow * NTOT + n0 + bc4 + it * 32);

    for (int ch = 0; ch < NCH; ch++) {
        // ---- round regs -> smem ----
#pragma unroll
        for (int it = 0; it < 4; it++) {
            int r = arow + it * 32;
            float4 v = aReg[it];
            *(uint2*)&sAh[r * A_STRIDE + ac4] =
                make_uint2(pack_h2(__float2half(v.x), __float2half(v.y)),
                           pack_h2(__float2half(v.z), __float2half(v.w)));
        }
#pragma unroll
        for (int it = 0; it < 4; it++) {
            int c = bc4 + it * 32;
            float4 v = bReg[it];
            *(uint2*)&sBh[brow * B_STRIDE + c] =
                make_uint2(pack_h2(__float2half(v.x), __float2half(v.y)),
                           pack_h2(__float2half(v.z), __float2half(v.w)));
        }
        __syncthreads();

        // ---- prefetch next chunk into registers (LDG in flight over compute) ----
        if (ch + 1 < NCH) {
            int kn = (ch + 1) * 32;
#pragma unroll
            for (int it = 0; it < 4; it++)
                aReg[it] = *(const float4*)(Ap + (size_t)(arow + it * 32) * KTOT + kn + ac4);
#pragma unroll
            for (int it = 0; it < 4; it++)
                bReg[it] = *(const float4*)(Bp + (size_t)(kn + brow) * NTOT + n0 + bc4 + it * 32);
        }

        // ---- compute: 2 k16 steps, 1 term ----
#pragma unroll
        for (int ks = 0; ks < 2; ks++) {
            uint32_t ah[4][4];
#pragma unroll
            for (int mi = 0; mi < 4; mi++) {
                int r = wm * 64 + mi * 16 + (lane & 15);
                uint32_t off = (uint32_t)(r * (A_STRIDE * 2) + ks * 32 + ((lane >> 4) << 4));
                ldmat_x4(ah[mi], aAh + off);
            }
#pragma unroll
            for (int p = 0; p < 2; p++) {
                int j = lane >> 3, i = lane & 7;
                int kk = ks * 16 + (j & 1) * 8 + i;
                int nn = wn * 32 + p * 16 + (j >> 1) * 8;
                uint32_t off = (uint32_t)(kk * (B_STRIDE * 2) + nn * 2);
                uint32_t b4[4];
                ldmat_x4_t(b4, aBh + off);
#pragma unroll
                for (int ni2 = 0; ni2 < 2; ni2++) {
                    int ni = p * 2 + ni2;
                    const uint32_t* bp2 = &b4[ni2 * 2];
#pragma unroll
                    for (int mi = 0; mi < 4; mi++)
                        mma16816(acc[mi][ni], ah[mi], bp2);
                }
            }
        }
        __syncthreads();
    }

    // ---- epilogue: bias (+gelu for FC1), fp32 stores ----
#pragma unroll
    for (int mi = 0; mi < 4; mi++) {
        int rbase = row0 + wm * 64 + mi * 16 + (lane >> 2);
#pragma unroll
        for (int ni = 0; ni < 4; ni++) {
            int col_l = wn * 32 + ni * 8 + ((lane & 3) << 1);
            float b0 = bp[n0 + col_l], b1 = bp[n0 + col_l + 1];
#pragma unroll
            for (int hh = 0; hh < 2; hh++) {
                int row = rbase + hh * 8;
                float v0 = acc[mi][ni][hh * 2]     + b0;
                float v1 = acc[mi][ni][hh * 2 + 1] + b1;
                size_t g = (size_t)row * NTOT + n0 + col_l;
                if (FC1) {
                    v0 = gelu_exact(v0); v1 = gelu_exact(v1);
                    *(float2*)(d_h + g) = make_float2(v0, v1);
                } else {
                    *(float2*)(d_y + g) = make_float2(v0, v1);
                }
            }
        }
    }
}

// out[i] = w0 * Y[s0] + w1 * Y[s1]
__global__ void combine_kernel(float* __restrict__ out) {
    int i = blockIdx.x;
    int s0 = d_s0[i], s1 = d_s1[i];
    float w0 = (s0 >= 0) ? d_g0[i] : 0.0f;
    float w1 = (s1 >= 0) ? d_g1[i] : 0.0f;
    float4 r = make_float4(0.f, 0.f, 0.f, 0.f);
    if (s0 >= 0) {
        float4 a = ((const float4*)(d_y + (size_t)s0 * DIM))[threadIdx.x];
        r.x += w0 * a.x; r.y += w0 * a.y; r.z += w0 * a.z; r.w += w0 * a.w;
    }
    if (s1 >= 0) {
        float4 a = ((const float4*)(d_y + (size_t)s1 * DIM))[threadIdx.x];
        r.x += w1 * a.x; r.y += w1 * a.y; r.z += w1 * a.z; r.w += w1 * a.w;
    }
    ((float4*)(out + (size_t)i * DIM))[threadIdx.x] = r;
}

__global__ void laux_kernel(float* __restrict__ out, int out_size) {
    if (threadIdx.x == 0 && out_size > NTOK * DIM) {
        float lx = 0.0f;
        for (int e = 0; e < NEXP; e++) {
            float me = d_me[e] / (float)NTOK;
            float ce = (float)d_cnt0[e] / (float)NTOK;
            lx += me * ce;
        }
        out[NTOK * DIM] = lx * (float)NEXP;
    }
}

// ---------------- launch ---------------------------------------------------
extern "C" void kernel_launch(void* const* d_in, const int* in_sizes, int n_in,
                              void* d_out, int out_size) {
    const float* x     = (const float*)d_in[0];
    const float* wg    = (const float*)d_in[1];
    const float* fc1_w = (const float*)d_in[2];
    const float* fc1_b = (const float*)d_in[3];
    const float* fc2_w = (const float*)d_in[4];
    const float* fc2_b = (const float*)d_in[5];
    float* out = (float*)d_out;

    zero_small_kernel<<<1, 32>>>();
    gate_kernel<<<NTOK / 8, 256>>>(x, wg);
    rank_kernel<<<NTOK / 256, 256>>>();
    scatter_kernel<<<NTOK, 256>>>(x);

    // FC1: A=d_disp [EC][DIM], B=fc1_w [E][DIM][HID] -> d_h (gelu+bias)
    mma_gemm_kernel<DIM, HID, true><<<dim3(HID / 128, EC / 128), 256>>>(fc1_w, fc1_b);
    // FC2: A=d_h [EC][HID],   B=fc2_w [E][HID][DIM] -> d_y (bias)
    mma_gemm_kernel<HID, DIM, false><<<dim3(DIM / 128, EC / 128), 256>>>(fc2_w, fc2_b);

    combine_kernel<<<NTOK, 256>>>(out);
    laux_kernel<<<1, 32>>>(out, out_size);
}